// round 5
// baseline (speedup 1.0000x reference)
#include <cuda_runtime.h>
#include <cuda_bf16.h>
#include <math.h>

// Problem constants (fixed by the reference)
#define B_DIM 128
#define S_DIM 512
#define K_DIM 137
#define D_DIM (2 * K_DIM)      // 274
#define NCONN (K_DIM - 1)      // 136
#define WARPS_PER_BLOCK 16
#define THREADS (WARPS_PER_BLOCK * 32)       // 512
#define N_ITEMS (B_DIM * S_DIM)              // 65536
#define N_BLOCKS (N_ITEMS / WARPS_PER_BLOCK) // 4096
#define THREADS_F 256

#define FULL_MASK 0xffffffffu

// Allocation-free scratch. Written unconditionally by every block each run.
// Finalize kernel (next graph node) reads it; stream ordering = visibility.
__device__ float2 g_partials[N_BLOCKS];

// One warp handles one (b, s) item.
// Phase 1: batch ALL global loads into register arrays (max MLP).
// Phase 2: compute bone diffs via register shuffles + pose L1.
__global__ __launch_bounds__(THREADS) void t2p_main_kernel(
    const float* __restrict__ pred,   // [128, 512, 274]
    const float* __restrict__ tgt,    // [128, 2, 512, 137]
    const int*   __restrict__ tlen)   // [128]
{
    __shared__ float s_pose[WARPS_PER_BLOCK];
    __shared__ float s_bone[WARPS_PER_BLOCK];

    const int warp = threadIdx.x >> 5;
    const int lane = threadIdx.x & 31;
    const int item = blockIdx.x * WARPS_PER_BLOCK + warp;
    const int b = item >> 9;   // item / 512
    const int s = item & 511;  // item % 512

    float pose_sum = 0.0f;
    float bone_sum = 0.0f;

    const int L = __ldg(&tlen[b]);
    const bool bone_valid = (s < L);       // warp-uniform
    const bool pose_valid = (s < L - 1);   // implies row s+1 exists (L <= S)

    if (bone_valid) {
        const float2* __restrict__ p2 = (const float2*)(pred + (size_t)item * D_DIM);
        const float*  __restrict__ t0 = tgt + ((size_t)(2 * b)     * S_DIM + s) * K_DIM;
        const float*  __restrict__ t1 = tgt + ((size_t)(2 * b + 1) * S_DIM + s) * K_DIM;

        // ---- Phase 1: load everything into registers, no arithmetic ----
        float px[5], py[5];          // pred keypoints (x, y)
        float a0[5], a1[5];          // target row s   (x, y)
        float c0[5], c1[5];          // target row s+1 (x, y), pose only

        #pragma unroll
        for (int j = 0; j < 5; j++) {
            const int  k  = (j < 4) ? (lane + 32 * j) : (128 + lane);
            const bool ok = (j < 4) || (lane < 9);
            px[j] = 0.0f; py[j] = 0.0f; a0[j] = 0.0f; a1[j] = 0.0f;
            if (ok) {
                float2 p = __ldg(&p2[k]);
                px[j] = p.x; py[j] = p.y;
                a0[j] = __ldg(&t0[k]);
                a1[j] = __ldg(&t1[k]);
            }
        }
        if (pose_valid) {
            #pragma unroll
            for (int j = 0; j < 5; j++) {
                const int  k  = (j < 4) ? (lane + 32 * j) : (128 + lane);
                const bool ok = (j < 4) || (lane < 9);
                c0[j] = px[j]; c1[j] = py[j];   // makes |p - c| = 0 on dead lanes
                if (ok) {
                    c0[j] = __ldg(&t0[k + K_DIM]);
                    c1[j] = __ldg(&t1[k + K_DIM]);
                }
            }
        }

        // ---- Phase 2: compute ----
        float ex[5], ey[5];
        #pragma unroll
        for (int j = 0; j < 5; j++) {
            ex[j] = px[j] - a0[j];
            ey[j] = py[j] - a1[j];
        }
        if (pose_valid) {
            #pragma unroll
            for (int j = 0; j < 5; j++) {
                pose_sum += fabsf(px[j] - c0[j]) + fabsf(py[j] - c1[j]);
            }
        }

        // Bone: d[k] = e[k+1] - e[k] via shuffles.
        // e[k+1]: lane<31 -> lane+1 same j; lane==31 -> lane 0 of j+1.
        #pragma unroll
        for (int j = 0; j < 4; j++) {
            float nx_dn = __shfl_down_sync(FULL_MASK, ex[j], 1);
            float ny_dn = __shfl_down_sync(FULL_MASK, ey[j], 1);
            float nx_w0 = __shfl_sync(FULL_MASK, ex[j + 1], 0);
            float ny_w0 = __shfl_sync(FULL_MASK, ey[j + 1], 0);
            float nx = (lane == 31) ? nx_w0 : nx_dn;
            float ny = (lane == 31) ? ny_w0 : ny_dn;
            float dx = nx - ex[j];
            float dy = ny - ey[j];
            bone_sum = fmaf(dx, dx, bone_sum);
            bone_sum = fmaf(dy, dy, bone_sum);
        }
        {   // j = 4: diffs for k = 128..135 -> lanes 0..7
            float nx_dn = __shfl_down_sync(FULL_MASK, ex[4], 1);
            float ny_dn = __shfl_down_sync(FULL_MASK, ey[4], 1);
            if (lane < 8) {
                float dx = nx_dn - ex[4];
                float dy = ny_dn - ey[4];
                bone_sum = fmaf(dx, dx, bone_sum);
                bone_sum = fmaf(dy, dy, bone_sum);
            }
        }
    }

    // Warp reduce
    #pragma unroll
    for (int o = 16; o > 0; o >>= 1) {
        pose_sum += __shfl_xor_sync(FULL_MASK, pose_sum, o);
        bone_sum += __shfl_xor_sync(FULL_MASK, bone_sum, o);
    }
    if (lane == 0) {
        s_pose[warp] = pose_sum;
        s_bone[warp] = bone_sum;
    }
    __syncthreads();

    // Plain per-block partial store — no fence, no atomic.
    if (threadIdx.x == 0) {
        float ps = 0.0f, bs = 0.0f;
        #pragma unroll
        for (int w = 0; w < WARPS_PER_BLOCK; w++) {
            ps += s_pose[w];
            bs += s_bone[w];
        }
        g_partials[blockIdx.x] = make_float2(ps, bs);
    }
}

// Single block, 256 threads: reduce 4096 float2 partials (32 KB, L2-hot)
// via float4 loads (8 independent loads/thread), then loss math.
__global__ __launch_bounds__(THREADS_F) void t2p_finalize_kernel(
    const int* __restrict__ tlen,
    float*     __restrict__ out)
{
    __shared__ double r_p[THREADS_F / 32];
    __shared__ double r_b[THREADS_F / 32];
    __shared__ int    s_len;

    const int warp = threadIdx.x >> 5;
    const int lane = threadIdx.x & 31;

    const float4* __restrict__ p4 = (const float4*)g_partials;  // 2048 float4

    // 8 independent loads per thread, batched
    float4 v[8];
    #pragma unroll
    for (int i = 0; i < 8; i++) {
        v[i] = __ldg(&p4[threadIdx.x + THREADS_F * i]);
    }
    double dp = 0.0, db = 0.0;
    #pragma unroll
    for (int i = 0; i < 8; i++) {
        dp += (double)v[i].x + (double)v[i].z;
        db += (double)v[i].y + (double)v[i].w;
    }
    #pragma unroll
    for (int o = 16; o > 0; o >>= 1) {
        dp += __shfl_xor_sync(FULL_MASK, dp, o);
        db += __shfl_xor_sync(FULL_MASK, db, o);
    }
    if (lane == 0) {
        r_p[warp] = dp;
        r_b[warp] = db;
    }
    // warp 0 also sums target_length (128 ints, 4 per lane)
    if (warp == 0) {
        int lsum = 0;
        #pragma unroll
        for (int i = 0; i < 4; i++) lsum += __ldg(&tlen[lane + 32 * i]);
        #pragma unroll
        for (int o = 16; o > 0; o >>= 1)
            lsum += __shfl_xor_sync(FULL_MASK, lsum, o);
        if (lane == 0) s_len = lsum;
    }
    __syncthreads();

    if (threadIdx.x == 0) {
        double pose_acc = 0.0, bone_acc = 0.0;
        #pragma unroll
        for (int w = 0; w < THREADS_F / 32; w++) {
            pose_acc += r_p[w];
            bone_acc += r_b[w];
        }
        int len_total = s_len;
        double mask_sum = (double)len_total;            // sum(L)
        double pose_den = (double)(len_total - B_DIM);  // sum(L-1)

        double pose_loss = pose_acc / (double)D_DIM / pose_den;
        double bone_loss = bone_acc * 0.5 / ((double)NCONN + 1e-8) / mask_sum;
        double total     = pose_loss + 0.1 * bone_loss;

        out[0] = (float)total;
        out[1] = (float)pose_loss;
        out[2] = (float)bone_loss;
    }
}

extern "C" void kernel_launch(void* const* d_in, const int* in_sizes, int n_in,
                              void* d_out, int out_size) {
    const float* pred = (const float*)d_in[0];   // [128, 512, 274] f32
    const float* tgt  = (const float*)d_in[1];   // [128, 2, 512, 137] f32
    const int*   tlen = (const int*)d_in[2];     // [128] i32
    float* out = (float*)d_out;                  // [3] f32: total, pose, bone

    t2p_main_kernel<<<N_BLOCKS, THREADS>>>(pred, tgt, tlen);
    t2p_finalize_kernel<<<1, THREADS_F>>>(tlen, out);
}

// round 6
// speedup vs baseline: 1.1081x; 1.1081x over previous
#include <cuda_runtime.h>
#include <cuda_bf16.h>
#include <math.h>

// Problem constants (fixed by the reference)
#define B_DIM 128
#define S_DIM 512
#define K_DIM 137
#define D_DIM (2 * K_DIM)      // 274
#define NCONN (K_DIM - 1)      // 136
#define WARPS_PER_BLOCK 16
#define THREADS (WARPS_PER_BLOCK * 32)       // 512
#define N_ITEMS (B_DIM * S_DIM)              // 65536
#define N_BLOCKS (N_ITEMS / WARPS_PER_BLOCK) // 4096
#define THREADS_F 256

#define FULL_MASK 0xffffffffu

// Allocation-free scratch. Written unconditionally by every block each run.
// Finalize kernel (next graph node) reads it; stream ordering = visibility.
__device__ float2 g_partials[N_BLOCKS];

// One warp handles one (b, s) item. Bone diffs via register shuffles.
// (R4 main kernel, unchanged — proven fastest variant.)
__global__ __launch_bounds__(THREADS) void t2p_main_kernel(
    const float* __restrict__ pred,   // [128, 512, 274]
    const float* __restrict__ tgt,    // [128, 2, 512, 137]
    const int*   __restrict__ tlen)   // [128]
{
    __shared__ float s_pose[WARPS_PER_BLOCK];
    __shared__ float s_bone[WARPS_PER_BLOCK];

    const int warp = threadIdx.x >> 5;
    const int lane = threadIdx.x & 31;
    const int item = blockIdx.x * WARPS_PER_BLOCK + warp;
    const int b = item >> 9;   // item / 512
    const int s = item & 511;  // item % 512

    float pose_sum = 0.0f;
    float bone_sum = 0.0f;

    const int L = __ldg(&tlen[b]);
    const bool bone_valid = (s < L);       // warp-uniform
    const bool pose_valid = (s < L - 1);   // implies s+1 <= S-1 (L <= S)

    if (bone_valid) {
        const float2* __restrict__ p2 = (const float2*)(pred + (size_t)item * D_DIM);
        const float*  __restrict__ t0 = tgt + ((size_t)(2 * b)     * S_DIM + s) * K_DIM;
        const float*  __restrict__ t1 = tgt + ((size_t)(2 * b + 1) * S_DIM + s) * K_DIM;

        // Register-resident errors: lane holds e[k] for k = lane + 32*j.
        float ex[5], ey[5];

        #pragma unroll
        for (int j = 0; j < 4; j++) {
            const int k = lane + 32 * j;
            float2 p  = __ldg(&p2[k]);
            float  a0 = __ldg(&t0[k]);
            float  a1 = __ldg(&t1[k]);
            ex[j] = p.x - a0;
            ey[j] = p.y - a1;
            if (pose_valid) {
                // next timestep rows are contiguous at +K
                pose_sum += fabsf(p.x - __ldg(&t0[k + K_DIM]))
                          + fabsf(p.y - __ldg(&t1[k + K_DIM]));
            }
        }
        // j = 4 partial tail: k = 128 + lane, lanes 0..8 (k <= 136)
        ex[4] = 0.0f; ey[4] = 0.0f;
        if (lane < 9) {
            const int k = 128 + lane;
            float2 p = __ldg(&p2[k]);
            ex[4] = p.x - __ldg(&t0[k]);
            ey[4] = p.y - __ldg(&t1[k]);
            if (pose_valid) {
                pose_sum += fabsf(p.x - __ldg(&t0[k + K_DIM]))
                          + fabsf(p.y - __ldg(&t1[k + K_DIM]));
            }
        }

        // Bone: d[k] = e[k+1] - e[k] via shuffles.
        // e[k+1]: lane<31 -> lane+1 same j; lane==31 -> lane 0 of j+1.
        #pragma unroll
        for (int j = 0; j < 4; j++) {
            float nx_dn = __shfl_down_sync(FULL_MASK, ex[j], 1);
            float ny_dn = __shfl_down_sync(FULL_MASK, ey[j], 1);
            float nx_w0 = __shfl_sync(FULL_MASK, ex[j + 1], 0);
            float ny_w0 = __shfl_sync(FULL_MASK, ey[j + 1], 0);
            float nx = (lane == 31) ? nx_w0 : nx_dn;
            float ny = (lane == 31) ? ny_w0 : ny_dn;
            float dx = nx - ex[j];
            float dy = ny - ey[j];
            bone_sum = fmaf(dx, dx, bone_sum);
            bone_sum = fmaf(dy, dy, bone_sum);
        }
        {   // j = 4: diffs for k = 128..135 -> lanes 0..7
            float nx_dn = __shfl_down_sync(FULL_MASK, ex[4], 1);
            float ny_dn = __shfl_down_sync(FULL_MASK, ey[4], 1);
            if (lane < 8) {
                float dx = nx_dn - ex[4];
                float dy = ny_dn - ey[4];
                bone_sum = fmaf(dx, dx, bone_sum);
                bone_sum = fmaf(dy, dy, bone_sum);
            }
        }
    }

    // Warp reduce
    #pragma unroll
    for (int o = 16; o > 0; o >>= 1) {
        pose_sum += __shfl_xor_sync(FULL_MASK, pose_sum, o);
        bone_sum += __shfl_xor_sync(FULL_MASK, bone_sum, o);
    }
    if (lane == 0) {
        s_pose[warp] = pose_sum;
        s_bone[warp] = bone_sum;
    }
    __syncthreads();

    // Plain per-block partial store — no fence, no atomic.
    if (threadIdx.x == 0) {
        float ps = 0.0f, bs = 0.0f;
        #pragma unroll
        for (int w = 0; w < WARPS_PER_BLOCK; w++) {
            ps += s_pose[w];
            bs += s_bone[w];
        }
        g_partials[blockIdx.x] = make_float2(ps, bs);
    }
}

// Single block: reduce 4096 float2 partials + loss math — ALL FP32.
// (FP64 divides/adds were the R4/R5 finalize bottleneck: DDIV is emulated,
// DADD lat ~47; fp32 tree reduction has rel error ~1e-6 << 1e-3 threshold.)
__global__ __launch_bounds__(THREADS_F) void t2p_finalize_kernel(
    const int* __restrict__ tlen,
    float*     __restrict__ out)
{
    __shared__ float r_p[THREADS_F / 32];
    __shared__ float r_b[THREADS_F / 32];
    __shared__ int   s_len;

    const int warp = threadIdx.x >> 5;
    const int lane = threadIdx.x & 31;

    const float4* __restrict__ p4 = (const float4*)g_partials;  // 2048 float4

    // 8 independent float4 loads per thread (batched), fp32 accumulate.
    float dp = 0.0f, db = 0.0f;
    #pragma unroll
    for (int i = 0; i < 8; i++) {
        float4 v = __ldg(&p4[threadIdx.x + THREADS_F * i]);
        dp += v.x + v.z;
        db += v.y + v.w;
    }
    #pragma unroll
    for (int o = 16; o > 0; o >>= 1) {
        dp += __shfl_xor_sync(FULL_MASK, dp, o);
        db += __shfl_xor_sync(FULL_MASK, db, o);
    }
    if (lane == 0) {
        r_p[warp] = dp;
        r_b[warp] = db;
    }
    // warp 0 also sums target_length (128 ints, 4 per lane)
    if (warp == 0) {
        int lsum = 0;
        #pragma unroll
        for (int i = 0; i < 4; i++) lsum += __ldg(&tlen[lane + 32 * i]);
        #pragma unroll
        for (int o = 16; o > 0; o >>= 1)
            lsum += __shfl_xor_sync(FULL_MASK, lsum, o);
        if (lane == 0) s_len = lsum;
    }
    __syncthreads();

    if (threadIdx.x == 0) {
        float pose_acc = 0.0f, bone_acc = 0.0f;
        #pragma unroll
        for (int w = 0; w < THREADS_F / 32; w++) {
            pose_acc += r_p[w];
            bone_acc += r_b[w];
        }
        float len_total = (float)s_len;
        float mask_sum  = len_total;                    // sum(L)
        float pose_den  = len_total - (float)B_DIM;     // sum(L-1)

        float pose_loss = pose_acc / ((float)D_DIM * pose_den);
        float bone_loss = bone_acc * 0.5f / (((float)NCONN + 1e-8f) * mask_sum);
        float total     = pose_loss + 0.1f * bone_loss;

        out[0] = total;
        out[1] = pose_loss;
        out[2] = bone_loss;
    }
}

extern "C" void kernel_launch(void* const* d_in, const int* in_sizes, int n_in,
                              void* d_out, int out_size) {
    const float* pred = (const float*)d_in[0];   // [128, 512, 274] f32
    const float* tgt  = (const float*)d_in[1];   // [128, 2, 512, 137] f32
    const int*   tlen = (const int*)d_in[2];     // [128] i32
    float* out = (float*)d_out;                  // [3] f32: total, pose, bone

    t2p_main_kernel<<<N_BLOCKS, THREADS>>>(pred, tgt, tlen);
    t2p_finalize_kernel<<<1, THREADS_F>>>(tlen, out);
}

// round 7
// speedup vs baseline: 1.1529x; 1.0405x over previous
#include <cuda_runtime.h>
#include <cuda_bf16.h>
#include <math.h>

// Problem constants (fixed by the reference)
#define B_DIM 128
#define S_DIM 512
#define K_DIM 137
#define D_DIM (2 * K_DIM)      // 274
#define NCONN (K_DIM - 1)      // 136
#define WARPS_PER_BLOCK 16
#define THREADS (WARPS_PER_BLOCK * 32)       // 512
#define N_ITEMS (B_DIM * S_DIM)              // 65536
#define N_BLOCKS (N_ITEMS / WARPS_PER_BLOCK) // 4096
#define THREADS_F 256

#define FULL_MASK 0xffffffffu

// Allocation-free scratch. Written unconditionally by every block each run.
__device__ float2 g_partials[N_BLOCKS];

// One warp handles one (b, s) item. Bone diffs via register shuffles.
// (R4 main kernel, unchanged — proven fastest variant.)
__global__ __launch_bounds__(THREADS) void t2p_main_kernel(
    const float* __restrict__ pred,   // [128, 512, 274]
    const float* __restrict__ tgt,    // [128, 2, 512, 137]
    const int*   __restrict__ tlen)   // [128]
{
    __shared__ float s_pose[WARPS_PER_BLOCK];
    __shared__ float s_bone[WARPS_PER_BLOCK];

    const int warp = threadIdx.x >> 5;
    const int lane = threadIdx.x & 31;
    const int item = blockIdx.x * WARPS_PER_BLOCK + warp;
    const int b = item >> 9;   // item / 512
    const int s = item & 511;  // item % 512

    float pose_sum = 0.0f;
    float bone_sum = 0.0f;

    const int L = __ldg(&tlen[b]);
    const bool bone_valid = (s < L);       // warp-uniform
    const bool pose_valid = (s < L - 1);   // implies s+1 <= S-1 (L <= S)

    if (bone_valid) {
        const float2* __restrict__ p2 = (const float2*)(pred + (size_t)item * D_DIM);
        const float*  __restrict__ t0 = tgt + ((size_t)(2 * b)     * S_DIM + s) * K_DIM;
        const float*  __restrict__ t1 = tgt + ((size_t)(2 * b + 1) * S_DIM + s) * K_DIM;

        // Register-resident errors: lane holds e[k] for k = lane + 32*j.
        float ex[5], ey[5];

        #pragma unroll
        for (int j = 0; j < 4; j++) {
            const int k = lane + 32 * j;
            float2 p  = __ldg(&p2[k]);
            float  a0 = __ldg(&t0[k]);
            float  a1 = __ldg(&t1[k]);
            ex[j] = p.x - a0;
            ey[j] = p.y - a1;
            if (pose_valid) {
                // next timestep rows are contiguous at +K
                pose_sum += fabsf(p.x - __ldg(&t0[k + K_DIM]))
                          + fabsf(p.y - __ldg(&t1[k + K_DIM]));
            }
        }
        // j = 4 partial tail: k = 128 + lane, lanes 0..8 (k <= 136)
        ex[4] = 0.0f; ey[4] = 0.0f;
        if (lane < 9) {
            const int k = 128 + lane;
            float2 p = __ldg(&p2[k]);
            ex[4] = p.x - __ldg(&t0[k]);
            ey[4] = p.y - __ldg(&t1[k]);
            if (pose_valid) {
                pose_sum += fabsf(p.x - __ldg(&t0[k + K_DIM]))
                          + fabsf(p.y - __ldg(&t1[k + K_DIM]));
            }
        }

        // Bone: d[k] = e[k+1] - e[k] via shuffles.
        // e[k+1]: lane<31 -> lane+1 same j; lane==31 -> lane 0 of j+1.
        #pragma unroll
        for (int j = 0; j < 4; j++) {
            float nx_dn = __shfl_down_sync(FULL_MASK, ex[j], 1);
            float ny_dn = __shfl_down_sync(FULL_MASK, ey[j], 1);
            float nx_w0 = __shfl_sync(FULL_MASK, ex[j + 1], 0);
            float ny_w0 = __shfl_sync(FULL_MASK, ey[j + 1], 0);
            float nx = (lane == 31) ? nx_w0 : nx_dn;
            float ny = (lane == 31) ? ny_w0 : ny_dn;
            float dx = nx - ex[j];
            float dy = ny - ey[j];
            bone_sum = fmaf(dx, dx, bone_sum);
            bone_sum = fmaf(dy, dy, bone_sum);
        }
        {   // j = 4: diffs for k = 128..135 -> lanes 0..7
            float nx_dn = __shfl_down_sync(FULL_MASK, ex[4], 1);
            float ny_dn = __shfl_down_sync(FULL_MASK, ey[4], 1);
            if (lane < 8) {
                float dx = nx_dn - ex[4];
                float dy = ny_dn - ey[4];
                bone_sum = fmaf(dx, dx, bone_sum);
                bone_sum = fmaf(dy, dy, bone_sum);
            }
        }
    }

    // Warp reduce
    #pragma unroll
    for (int o = 16; o > 0; o >>= 1) {
        pose_sum += __shfl_xor_sync(FULL_MASK, pose_sum, o);
        bone_sum += __shfl_xor_sync(FULL_MASK, bone_sum, o);
    }
    if (lane == 0) {
        s_pose[warp] = pose_sum;
        s_bone[warp] = bone_sum;
    }
    __syncthreads();

    // Plain per-block partial store — no fence, no atomic.
    if (threadIdx.x == 0) {
        float ps = 0.0f, bs = 0.0f;
        #pragma unroll
        for (int w = 0; w < WARPS_PER_BLOCK; w++) {
            ps += s_pose[w];
            bs += s_bone[w];
        }
        g_partials[blockIdx.x] = make_float2(ps, bs);
    }
}

// Finalize, launched with PDL (programmatic stream serialization): its
// prologue overlaps the main kernel; cudaGridDependencySynchronize() blocks
// until main completes (and makes g_partials visible). Work independent of
// main (tlen sum) runs BEFORE the sync to maximize overlap.
__global__ __launch_bounds__(THREADS_F) void t2p_finalize_kernel(
    const int* __restrict__ tlen,
    float*     __restrict__ out)
{
    __shared__ float r_p[THREADS_F / 32];
    __shared__ float r_b[THREADS_F / 32];
    __shared__ int   s_len;

    const int warp = threadIdx.x >> 5;
    const int lane = threadIdx.x & 31;

    // ---- Pre-sync work: does not depend on main kernel output ----
    if (warp == 0) {
        int lsum = 0;
        #pragma unroll
        for (int i = 0; i < 4; i++) lsum += __ldg(&tlen[lane + 32 * i]);
        #pragma unroll
        for (int o = 16; o > 0; o >>= 1)
            lsum += __shfl_xor_sync(FULL_MASK, lsum, o);
        if (lane == 0) s_len = lsum;
    }

    // ---- Wait for the main kernel (memory ops included) ----
    cudaGridDependencySynchronize();

    const float4* __restrict__ p4 = (const float4*)g_partials;  // 2048 float4

    // 8 independent float4 loads per thread (batched), fp32 accumulate.
    float dp = 0.0f, db = 0.0f;
    #pragma unroll
    for (int i = 0; i < 8; i++) {
        float4 v = __ldg(&p4[threadIdx.x + THREADS_F * i]);
        dp += v.x + v.z;
        db += v.y + v.w;
    }
    #pragma unroll
    for (int o = 16; o > 0; o >>= 1) {
        dp += __shfl_xor_sync(FULL_MASK, dp, o);
        db += __shfl_xor_sync(FULL_MASK, db, o);
    }
    if (lane == 0) {
        r_p[warp] = dp;
        r_b[warp] = db;
    }
    __syncthreads();

    if (threadIdx.x == 0) {
        float pose_acc = 0.0f, bone_acc = 0.0f;
        #pragma unroll
        for (int w = 0; w < THREADS_F / 32; w++) {
            pose_acc += r_p[w];
            bone_acc += r_b[w];
        }
        float len_total = (float)s_len;
        float mask_sum  = len_total;                    // sum(L)
        float pose_den  = len_total - (float)B_DIM;     // sum(L-1)

        float pose_loss = pose_acc / ((float)D_DIM * pose_den);
        float bone_loss = bone_acc * 0.5f / (((float)NCONN + 1e-8f) * mask_sum);
        float total     = pose_loss + 0.1f * bone_loss;

        out[0] = total;
        out[1] = pose_loss;
        out[2] = bone_loss;
    }
}

extern "C" void kernel_launch(void* const* d_in, const int* in_sizes, int n_in,
                              void* d_out, int out_size) {
    const float* pred = (const float*)d_in[0];   // [128, 512, 274] f32
    const float* tgt  = (const float*)d_in[1];   // [128, 2, 512, 137] f32
    const int*   tlen = (const int*)d_in[2];     // [128] i32
    float* out = (float*)d_out;                  // [3] f32: total, pose, bone

    t2p_main_kernel<<<N_BLOCKS, THREADS>>>(pred, tgt, tlen);

    // PDL launch: finalize prologue overlaps main; body gated by
    // cudaGridDependencySynchronize() inside the kernel.
    cudaLaunchConfig_t cfg = {};
    cfg.gridDim  = dim3(1, 1, 1);
    cfg.blockDim = dim3(THREADS_F, 1, 1);
    cfg.dynamicSmemBytes = 0;
    cfg.stream = 0;  // same (default) stream as the main kernel
    cudaLaunchAttribute attr[1];
    attr[0].id = cudaLaunchAttributeProgrammaticStreamSerialization;
    attr[0].val.programmaticStreamSerializationAllowed = 1;
    cfg.attrs = attr;
    cfg.numAttrs = 1;
    cudaLaunchKernelEx(&cfg, t2p_finalize_kernel, tlen, (float*)out);
}